// round 2
// baseline (speedup 1.0000x reference)
#include <cuda_runtime.h>
#include <cuda_bf16.h>
#include <stdint.h>

#define B_    8
#define L_    4096
#define D_    1024
#define A_    256
#define LC_   4352      // A_ + L_
#define KEEP_ 256
#define NSLICE 68       // salience grid.x; 68 * 64 rows = 4352

// -------- scratch (device globals; no allocation allowed) --------
__device__ float g_sal[B_ * LC_];
__device__ float g_part[B_ * NSLICE * D_];   // per-block partial column sums
__device__ int   g_topidx[B_ * KEEP_];
__device__ float g_ctx[B_ * D_];
__device__ float g_proj[B_ * D_];

// ---------------- K1: salience + per-block partial column sums ----------------
// grid: (NSLICE, B_), block 256 (8 warps). 64 rows/block, 8 rows/warp.
__global__ void k_salience(const float* __restrict__ x,
                           const float* __restrict__ active,
                           const float* __restrict__ wsal) {
    __shared__ float s_col[D_];
    const int b    = blockIdx.y;
    const int tid  = threadIdx.x;
    const int warp = tid >> 5;
    const int lane = tid & 31;

    for (int i = tid; i < D_; i += blockDim.x) s_col[i] = 0.f;

    float4 ws[8];
#pragma unroll
    for (int k = 0; k < 8; k++)
        ws[k] = *(const float4*)(wsal + k * 128 + lane * 4);
    float4 cs[8];
#pragma unroll
    for (int k = 0; k < 8; k++) cs[k] = make_float4(0.f, 0.f, 0.f, 0.f);

    __syncthreads();

    const int row0 = blockIdx.x * 64 + warp * 8;
#pragma unroll
    for (int r = 0; r < 8; r++) {
        const int t = row0 + r;
        const float* src = (t < A_)
            ? active + ((size_t)b * A_ + t) * D_
            : x      + ((size_t)b * L_ + (t - A_)) * D_;
        float dot = 0.f;
#pragma unroll
        for (int k = 0; k < 8; k++) {
            float4 v = *(const float4*)(src + k * 128 + lane * 4);
            dot += v.x * ws[k].x + v.y * ws[k].y + v.z * ws[k].z + v.w * ws[k].w;
            cs[k].x += v.x; cs[k].y += v.y; cs[k].z += v.z; cs[k].w += v.w;
        }
#pragma unroll
        for (int o = 16; o > 0; o >>= 1)
            dot += __shfl_down_sync(0xffffffffu, dot, o);
        if (lane == 0) g_sal[b * LC_ + t] = dot;
    }

    // per-warp column sums -> shared (atomic within block only) -> single STG
#pragma unroll
    for (int k = 0; k < 8; k++) {
        int d0 = k * 128 + lane * 4;
        atomicAdd(&s_col[d0 + 0], cs[k].x);
        atomicAdd(&s_col[d0 + 1], cs[k].y);
        atomicAdd(&s_col[d0 + 2], cs[k].z);
        atomicAdd(&s_col[d0 + 3], cs[k].w);
    }
    __syncthreads();
    float* dst = g_part + ((size_t)b * NSLICE + blockIdx.x) * D_;
    for (int i = tid; i < D_ / 4; i += blockDim.x)
        *(float4*)(dst + i * 4) = *(const float4*)(&s_col[i * 4]);
}

// ---------------- K2: exact top-256 (radix select), sorted ascending ----------------
__device__ __forceinline__ unsigned int order_key(float f) {
    unsigned int u = __float_as_uint(f);
    return u ^ ((u >> 31) ? 0xFFFFFFFFu : 0x80000000u);
}

__global__ void k_topk() {
    const int b   = blockIdx.x;
    const int tid = threadIdx.x;
    const int nt  = blockDim.x;

    __shared__ unsigned int skeys[LC_];
    __shared__ int          eqbuf[LC_];
    __shared__ unsigned int hist[256];
    __shared__ int          out_idx[KEEP_];
    __shared__ unsigned int s_prefix;
    __shared__ int          s_krem, s_ngt, s_neq;

    for (int i = tid; i < LC_; i += nt)
        skeys[i] = order_key(g_sal[b * LC_ + i]);
    if (tid == 0) { s_prefix = 0u; s_krem = KEEP_; s_ngt = 0; s_neq = 0; }
    __syncthreads();

    for (int pass = 0; pass < 4; pass++) {
        const int shift = 24 - 8 * pass;
        for (int i = tid; i < 256; i += nt) hist[i] = 0u;
        __syncthreads();
        const unsigned int pfx = s_prefix;
        for (int i = tid; i < LC_; i += nt) {
            unsigned int k = skeys[i];
            if (pass == 0 || (k >> (shift + 8)) == pfx)
                atomicAdd(&hist[(k >> shift) & 255u], 1u);
        }
        __syncthreads();
        if (tid == 0) {
            int cum = 0, krem = s_krem, sel = 0;
            for (int d = 255; d >= 0; d--) {
                cum += (int)hist[d];
                if (cum >= krem) { sel = d; s_krem = krem - (cum - (int)hist[d]); break; }
            }
            s_prefix = (pfx << 8) | (unsigned int)sel;
        }
        __syncthreads();
    }

    const unsigned int thr = s_prefix;
    const int rem = s_krem;

    for (int i = tid; i < LC_; i += nt) {
        unsigned int k = skeys[i];
        if (k > thr)       { int p = atomicAdd(&s_ngt, 1); out_idx[p] = i; }
        else if (k == thr) { int p = atomicAdd(&s_neq, 1); eqbuf[p]   = i; }
    }
    __syncthreads();
    const int ngt = s_ngt, neq = s_neq;
    for (int j = tid; j < neq; j += nt) {
        int v = eqbuf[j], c = 0;
        for (int m = 0; m < neq; m++) c += (eqbuf[m] < v);
        if (c < rem) out_idx[ngt + c] = v;
    }
    __syncthreads();

    for (int k = 2; k <= KEEP_; k <<= 1) {
        for (int j = k >> 1; j > 0; j >>= 1) {
            for (int t = tid; t < KEEP_; t += nt) {
                int partner = t ^ j;
                if (partner > t) {
                    int a0 = out_idx[t], a1 = out_idx[partner];
                    bool up = ((t & k) == 0);
                    if ((a0 > a1) == up) { out_idx[t] = a1; out_idx[partner] = a0; }
                }
            }
            __syncthreads();
        }
    }
    for (int t = tid; t < KEEP_; t += nt)
        g_topidx[b * KEEP_ + t] = out_idx[t];
}

// ---------------- K3: gather kept rows -> new_active (one warp per row) ----------------
// grid: (KEEP_/8, B_) = (32, B_), block 256 (8 warps); warp w copies row row0+w
__global__ void k_gather(const float* __restrict__ x,
                         const float* __restrict__ active,
                         float* __restrict__ new_active_out) {
    const int b    = blockIdx.y;
    const int warp = threadIdx.x >> 5;
    const int lane = threadIdx.x & 31;
    const int row  = blockIdx.x * 8 + warp;

    const int idx = g_topidx[b * KEEP_ + row];
    const float* src = (idx < A_)
        ? active + ((size_t)b * A_ + idx) * D_
        : x      + ((size_t)b * L_ + (idx - A_)) * D_;
    float* dst = new_active_out + ((size_t)b * KEEP_ + row) * D_;

    float4 v[8];
#pragma unroll
    for (int k = 0; k < 8; k++)
        v[k] = *(const float4*)(src + k * 128 + lane * 4);
#pragma unroll
    for (int k = 0; k < 8; k++)
        *(float4*)(dst + k * 128 + lane * 4) = v[k];
}

// ---------------- K4: reduce partials + keptsum + cold_new + ctx ----------------
// grid B_, block 1024; thread = one d
__global__ void k_ctx(const float* __restrict__ new_active,
                      const float* __restrict__ cold,
                      float* __restrict__ cold_out) {
    const int b = blockIdx.x;
    const int d = threadIdx.x;

    float tot = 0.f;
    const float* p = g_part + (size_t)b * NSLICE * D_ + d;
#pragma unroll 4
    for (int s = 0; s < NSLICE; s++) tot += p[(size_t)s * D_];

    float ks = 0.f;
    const float* na = new_active + (size_t)b * KEEP_ * D_ + d;
#pragma unroll 8
    for (int r = 0; r < KEEP_; r++) ks += na[(size_t)r * D_];

    const int i = b * D_ + d;
    const float dropped_mean = (tot - ks) * (1.0f / (float)(LC_ - KEEP_));
    const float cn = 0.9f * cold[i] + 0.1f * dropped_mean;
    cold_out[i] = cn;
    g_ctx[i] = ks * (1.0f / (float)KEEP_) + cn;
}

// ---------------- K5: proj[b,e] = sum_d ctx[b,d] * w_read[e,d] ----------------
// grid 32, block 256 (8 warps, 4 rows each)
__global__ void k_gemv(const float* __restrict__ wread) {
    __shared__ float4 sctx[B_ * 256];
    const int tid = threadIdx.x;
    for (int i = tid; i < B_ * 256; i += blockDim.x)
        sctx[i] = *(const float4*)(g_ctx + i * 4);
    __syncthreads();

    const int warp = tid >> 5, lane = tid & 31;
    for (int r = 0; r < 4; r++) {
        const int e = blockIdx.x * 32 + warp * 4 + r;
        const float* wr = wread + (size_t)e * D_;
        float acc[B_];
#pragma unroll
        for (int bb = 0; bb < B_; bb++) acc[bb] = 0.f;
#pragma unroll
        for (int k = 0; k < 8; k++) {
            float4 w = *(const float4*)(wr + k * 128 + lane * 4);
#pragma unroll
            for (int bb = 0; bb < B_; bb++) {
                float4 c = sctx[bb * 256 + k * 32 + lane];
                acc[bb] += w.x * c.x + w.y * c.y + w.z * c.z + w.w * c.w;
            }
        }
#pragma unroll
        for (int bb = 0; bb < B_; bb++) {
#pragma unroll
            for (int o = 16; o > 0; o >>= 1)
                acc[bb] += __shfl_down_sync(0xffffffffu, acc[bb], o);
            if (lane == 0) g_proj[bb * D_ + e] = acc[bb];
        }
    }
}

// ---------------- K6: x_out = x + proj (broadcast over l) ----------------
// grid: (L_/8, B_) = (512, B_), block 512; 8 rows/block, 2 float4 per row per thread
__global__ void k_addproj(const float* __restrict__ x,
                          float* __restrict__ xout) {
    const int b   = blockIdx.y;
    const int l0  = blockIdx.x * 8;
    const int tid = threadIdx.x;          // 512 threads -> 2048 floats = 2 rows per pass
    const int r0  = tid >> 8;             // 0..1
    const int c4  = (tid & 255) * 4;      // 0..1020

    const float4 p = *(const float4*)(g_proj + b * D_ + c4);
    const float* xs = x    + ((size_t)b * L_ + l0 + r0) * D_ + c4;
    float*       os = xout + ((size_t)b * L_ + l0 + r0) * D_ + c4;
#pragma unroll
    for (int r = 0; r < 8; r += 2) {
        float4 v = *(const float4*)(xs + (size_t)r * D_);
        v.x += p.x; v.y += p.y; v.z += p.z; v.w += p.w;
        *(float4*)(os + (size_t)r * D_) = v;
    }
}

// ---------------- launch ----------------
extern "C" void kernel_launch(void* const* d_in, const int* in_sizes, int n_in,
                              void* d_out, int out_size) {
    const float* x      = (const float*)d_in[0];   // [8,4096,1024]
    const float* active = (const float*)d_in[1];   // [8,256,1024]
    const float* cold   = (const float*)d_in[2];   // [8,1024]
    const float* w_sal  = (const float*)d_in[3];   // [1024]
    const float* w_read = (const float*)d_in[4];   // [1024,1024]

    float* xout       = (float*)d_out;
    float* new_active = xout + (size_t)in_sizes[0];
    float* cold_out   = new_active + (size_t)in_sizes[1];

    { dim3 grid(NSLICE, B_); k_salience<<<grid, 256>>>(x, active, w_sal); }
    k_topk<<<B_, 1024>>>();
    { dim3 grid(KEEP_ / 8, B_); k_gather<<<grid, 256>>>(x, active, new_active); }
    k_ctx<<<B_, 1024>>>(new_active, cold, cold_out);
    k_gemv<<<32, 256>>>(w_read);
    { dim3 grid(L_ / 8, B_); k_addproj<<<grid, 512>>>(x, xout); }
}

// round 3
// speedup vs baseline: 1.3452x; 1.3452x over previous
#include <cuda_runtime.h>
#include <cuda_bf16.h>
#include <stdint.h>

#define B_    8
#define L_    4096
#define D_    1024
#define A_    256
#define LC_   4352      // A_ + L_
#define KEEP_ 256
#define NSLICE 68       // salience partial slices (68 * 64 rows = 4352)
#define GSLICE 32       // gather partial slices  (32 * 8 rows = 256)

// -------- scratch (device globals; no allocation allowed) --------
__device__ float g_sal[B_ * LC_];
__device__ float g_part[B_ * NSLICE * D_];   // salience per-block column sums
__device__ float g_kpart[B_ * GSLICE * D_];  // gather per-block kept column sums
__device__ int   g_topidx[B_ * KEEP_];
__device__ float g_ctx[B_ * D_];
__device__ float g_proj[B_ * D_];

// ---------------- K1: salience + per-block partial column sums ----------------
// grid: (NSLICE, B_), block 256 (8 warps). 64 rows/block, 8 rows/warp.
__global__ void k_salience(const float* __restrict__ x,
                           const float* __restrict__ active,
                           const float* __restrict__ wsal) {
    __shared__ float s_col[D_];
    const int b    = blockIdx.y;
    const int tid  = threadIdx.x;
    const int warp = tid >> 5;
    const int lane = tid & 31;

    for (int i = tid; i < D_; i += blockDim.x) s_col[i] = 0.f;

    float4 ws[8];
#pragma unroll
    for (int k = 0; k < 8; k++)
        ws[k] = *(const float4*)(wsal + k * 128 + lane * 4);
    float4 cs[8];
#pragma unroll
    for (int k = 0; k < 8; k++) cs[k] = make_float4(0.f, 0.f, 0.f, 0.f);

    __syncthreads();

    const int row0 = blockIdx.x * 64 + warp * 8;
#pragma unroll
    for (int r = 0; r < 8; r++) {
        const int t = row0 + r;
        const float* src = (t < A_)
            ? active + ((size_t)b * A_ + t) * D_
            : x      + ((size_t)b * L_ + (t - A_)) * D_;
        float dot = 0.f;
#pragma unroll
        for (int k = 0; k < 8; k++) {
            float4 v = *(const float4*)(src + k * 128 + lane * 4);
            dot += v.x * ws[k].x + v.y * ws[k].y + v.z * ws[k].z + v.w * ws[k].w;
            cs[k].x += v.x; cs[k].y += v.y; cs[k].z += v.z; cs[k].w += v.w;
        }
#pragma unroll
        for (int o = 16; o > 0; o >>= 1)
            dot += __shfl_down_sync(0xffffffffu, dot, o);
        if (lane == 0) g_sal[b * LC_ + t] = dot;
    }

#pragma unroll
    for (int k = 0; k < 8; k++) {
        int d0 = k * 128 + lane * 4;
        atomicAdd(&s_col[d0 + 0], cs[k].x);
        atomicAdd(&s_col[d0 + 1], cs[k].y);
        atomicAdd(&s_col[d0 + 2], cs[k].z);
        atomicAdd(&s_col[d0 + 3], cs[k].w);
    }
    __syncthreads();
    float* dst = g_part + ((size_t)b * NSLICE + blockIdx.x) * D_;
    for (int i = tid; i < D_ / 4; i += blockDim.x)
        *(float4*)(dst + i * 4) = *(const float4*)(&s_col[i * 4]);
}

// ---------------- K2: exact top-256 (radix select), sorted ascending ----------------
__device__ __forceinline__ unsigned int order_key(float f) {
    unsigned int u = __float_as_uint(f);
    return u ^ ((u >> 31) ? 0xFFFFFFFFu : 0x80000000u);
}

__global__ void k_topk() {
    const int b   = blockIdx.x;
    const int tid = threadIdx.x;
    const int nt  = blockDim.x;

    __shared__ unsigned int skeys[LC_];
    __shared__ int          eqbuf[LC_];
    __shared__ unsigned int hist[256];
    __shared__ int          out_idx[KEEP_];
    __shared__ unsigned int s_prefix;
    __shared__ int          s_krem, s_ngt, s_neq;

    for (int i = tid; i < LC_; i += nt)
        skeys[i] = order_key(g_sal[b * LC_ + i]);
    if (tid == 0) { s_prefix = 0u; s_krem = KEEP_; s_ngt = 0; s_neq = 0; }
    __syncthreads();

    for (int pass = 0; pass < 4; pass++) {
        const int shift = 24 - 8 * pass;
        for (int i = tid; i < 256; i += nt) hist[i] = 0u;
        __syncthreads();
        const unsigned int pfx = s_prefix;
        for (int i = tid; i < LC_; i += nt) {
            unsigned int k = skeys[i];
            if (pass == 0 || (k >> (shift + 8)) == pfx)
                atomicAdd(&hist[(k >> shift) & 255u], 1u);
        }
        __syncthreads();
        if (tid == 0) {
            int cum = 0, krem = s_krem, sel = 0;
            for (int d = 255; d >= 0; d--) {
                cum += (int)hist[d];
                if (cum >= krem) { sel = d; s_krem = krem - (cum - (int)hist[d]); break; }
            }
            s_prefix = (pfx << 8) | (unsigned int)sel;
        }
        __syncthreads();
    }

    const unsigned int thr = s_prefix;
    const int rem = s_krem;

    for (int i = tid; i < LC_; i += nt) {
        unsigned int k = skeys[i];
        if (k > thr)       { int p = atomicAdd(&s_ngt, 1); out_idx[p] = i; }
        else if (k == thr) { int p = atomicAdd(&s_neq, 1); eqbuf[p]   = i; }
    }
    __syncthreads();
    const int ngt = s_ngt, neq = s_neq;
    for (int j = tid; j < neq; j += nt) {
        int v = eqbuf[j], c = 0;
        for (int m = 0; m < neq; m++) c += (eqbuf[m] < v);
        if (c < rem) out_idx[ngt + c] = v;
    }
    __syncthreads();

    for (int k = 2; k <= KEEP_; k <<= 1) {
        for (int j = k >> 1; j > 0; j >>= 1) {
            for (int t = tid; t < KEEP_; t += nt) {
                int partner = t ^ j;
                if (partner > t) {
                    int a0 = out_idx[t], a1 = out_idx[partner];
                    bool up = ((t & k) == 0);
                    if ((a0 > a1) == up) { out_idx[t] = a1; out_idx[partner] = a0; }
                }
            }
            __syncthreads();
        }
    }
    for (int t = tid; t < KEEP_; t += nt)
        g_topidx[b * KEEP_ + t] = out_idx[t];
}

// ---------------- K3: gather kept rows + per-block kept column sums ----------------
// grid: (GSLICE, B_) = (32, B_), block 256 (8 warps); warp w copies row blk*8+w
__global__ void k_gather(const float* __restrict__ x,
                         const float* __restrict__ active,
                         float* __restrict__ new_active_out) {
    __shared__ float s_col[D_];
    const int b    = blockIdx.y;
    const int tid  = threadIdx.x;
    const int warp = tid >> 5;
    const int lane = tid & 31;
    const int row  = blockIdx.x * 8 + warp;

    for (int i = tid; i < D_; i += blockDim.x) s_col[i] = 0.f;

    const int idx = g_topidx[b * KEEP_ + row];
    const float* src = (idx < A_)
        ? active + ((size_t)b * A_ + idx) * D_
        : x      + ((size_t)b * L_ + (idx - A_)) * D_;
    float* dst = new_active_out + ((size_t)b * KEEP_ + row) * D_;

    float4 v[8];
#pragma unroll
    for (int k = 0; k < 8; k++)
        v[k] = *(const float4*)(src + k * 128 + lane * 4);
    __syncthreads();   // s_col init done
#pragma unroll
    for (int k = 0; k < 8; k++) {
        *(float4*)(dst + k * 128 + lane * 4) = v[k];
        int d0 = k * 128 + lane * 4;
        atomicAdd(&s_col[d0 + 0], v[k].x);
        atomicAdd(&s_col[d0 + 1], v[k].y);
        atomicAdd(&s_col[d0 + 2], v[k].z);
        atomicAdd(&s_col[d0 + 3], v[k].w);
    }
    __syncthreads();
    float* kp = g_kpart + ((size_t)b * GSLICE + blockIdx.x) * D_;
    for (int i = tid; i < D_ / 4; i += blockDim.x)
        *(float4*)(kp + i * 4) = *(const float4*)(&s_col[i * 4]);
}

// ---------------- K4: reduce partials -> cold_new + ctx ----------------
// grid (D_/128, B_) = (8, B_), block 1024: 8 threads cooperate per d
__global__ void k_ctx(const float* __restrict__ cold,
                      float* __restrict__ cold_out) {
    __shared__ float st[8][128];
    __shared__ float sk[8][128];
    const int b  = blockIdx.y;
    const int d0 = blockIdx.x * 128;
    const int dx = threadIdx.x & 127;
    const int sy = threadIdx.x >> 7;

    float tot = 0.f;
    const float* p = g_part + (size_t)b * NSLICE * D_ + d0 + dx;
#pragma unroll
    for (int s = sy; s < NSLICE; s += 8) tot += p[(size_t)s * D_];

    float ks = 0.f;
    const float* kp = g_kpart + (size_t)b * GSLICE * D_ + d0 + dx;
#pragma unroll
    for (int s = sy; s < GSLICE; s += 8) ks += kp[(size_t)s * D_];

    st[sy][dx] = tot;
    sk[sy][dx] = ks;
    __syncthreads();
    if (sy == 0) {
        float t = 0.f, k = 0.f;
#pragma unroll
        for (int s = 0; s < 8; s++) { t += st[s][dx]; k += sk[s][dx]; }
        const int i = b * D_ + d0 + dx;
        const float dropped_mean = (t - k) * (1.0f / (float)(LC_ - KEEP_));
        const float cn = 0.9f * cold[i] + 0.1f * dropped_mean;
        cold_out[i] = cn;
        g_ctx[i] = k * (1.0f / (float)KEEP_) + cn;
    }
}

// ---------------- K5: proj[b,e] = sum_d ctx[b,d] * w_read[e,d] ----------------
// grid 32, block 256 (8 warps, 4 rows each)
__global__ void k_gemv(const float* __restrict__ wread) {
    __shared__ float4 sctx[B_ * 256];
    const int tid = threadIdx.x;
    for (int i = tid; i < B_ * 256; i += blockDim.x)
        sctx[i] = *(const float4*)(g_ctx + i * 4);
    __syncthreads();

    const int warp = tid >> 5, lane = tid & 31;
    for (int r = 0; r < 4; r++) {
        const int e = blockIdx.x * 32 + warp * 4 + r;
        const float* wr = wread + (size_t)e * D_;
        float acc[B_];
#pragma unroll
        for (int bb = 0; bb < B_; bb++) acc[bb] = 0.f;
#pragma unroll
        for (int k = 0; k < 8; k++) {
            float4 w = *(const float4*)(wr + k * 128 + lane * 4);
#pragma unroll
            for (int bb = 0; bb < B_; bb++) {
                float4 c = sctx[bb * 256 + k * 32 + lane];
                acc[bb] += w.x * c.x + w.y * c.y + w.z * c.z + w.w * c.w;
            }
        }
#pragma unroll
        for (int bb = 0; bb < B_; bb++) {
#pragma unroll
            for (int o = 16; o > 0; o >>= 1)
                acc[bb] += __shfl_down_sync(0xffffffffu, acc[bb], o);
            if (lane == 0) g_proj[bb * D_ + e] = acc[bb];
        }
    }
}

// ---------------- K6: x_out = x + proj (broadcast over l) ----------------
// grid: (L_/16, B_), block 256; 16 rows per block
__global__ void k_addproj(const float* __restrict__ x,
                          float* __restrict__ xout) {
    const int b   = blockIdx.y;
    const int l0  = blockIdx.x * 16;
    const int tid = threadIdx.x;
    const float4 p = *(const float4*)(g_proj + b * D_ + tid * 4);
    const float* xs = x    + ((size_t)b * L_ + l0) * D_;
    float*       os = xout + ((size_t)b * L_ + l0) * D_;
#pragma unroll 4
    for (int r = 0; r < 16; r++) {
        float4 v = *(const float4*)(xs + (size_t)r * D_ + tid * 4);
        v.x += p.x; v.y += p.y; v.z += p.z; v.w += p.w;
        *(float4*)(os + (size_t)r * D_ + tid * 4) = v;
    }
}

// ---------------- launch ----------------
extern "C" void kernel_launch(void* const* d_in, const int* in_sizes, int n_in,
                              void* d_out, int out_size) {
    const float* x      = (const float*)d_in[0];   // [8,4096,1024]
    const float* active = (const float*)d_in[1];   // [8,256,1024]
    const float* cold   = (const float*)d_in[2];   // [8,1024]
    const float* w_sal  = (const float*)d_in[3];   // [1024]
    const float* w_read = (const float*)d_in[4];   // [1024,1024]

    float* xout       = (float*)d_out;
    float* new_active = xout + (size_t)in_sizes[0];
    float* cold_out   = new_active + (size_t)in_sizes[1];

    { dim3 grid(NSLICE, B_); k_salience<<<grid, 256>>>(x, active, w_sal); }
    k_topk<<<B_, 1024>>>();
    { dim3 grid(GSLICE, B_); k_gather<<<grid, 256>>>(x, active, new_active); }
    { dim3 grid(D_ / 128, B_); k_ctx<<<grid, 1024>>>(cold, cold_out); }
    k_gemv<<<32, 256>>>(w_read);
    { dim3 grid(L_ / 16, B_); k_addproj<<<grid, 256>>>(x, xout); }
}

// round 4
// speedup vs baseline: 1.4751x; 1.0966x over previous
#include <cuda_runtime.h>
#include <cuda_bf16.h>
#include <stdint.h>

#define B_    8
#define L_    4096
#define D_    1024
#define A_    256
#define LC_   4352      // A_ + L_
#define KEEP_ 256
#define NSLICE 68       // salience partial slices (68 * 64 rows = 4352)
#define GSLICE 32       // gather partial slices  (32 * 8 rows = 256)

// -------- scratch (device globals; no allocation allowed) --------
__device__ float g_sal[B_ * LC_];
__device__ float g_part[B_ * NSLICE * D_];   // salience per-block column sums
__device__ float g_kpart[B_ * GSLICE * D_];  // gather per-block kept column sums
__device__ int   g_topidx[B_ * KEEP_];
__device__ float g_ctx[B_ * D_];
__device__ float g_proj[B_ * D_];

// ---------------- K1: salience + per-block partial column sums ----------------
// grid: (NSLICE, B_), block 256 (8 warps). 64 rows/block, 8 rows/warp.
__global__ void k_salience(const float* __restrict__ x,
                           const float* __restrict__ active,
                           const float* __restrict__ wsal) {
    __shared__ float s_col[D_];
    const int b    = blockIdx.y;
    const int tid  = threadIdx.x;
    const int warp = tid >> 5;
    const int lane = tid & 31;

    for (int i = tid; i < D_; i += blockDim.x) s_col[i] = 0.f;

    float4 ws[8];
#pragma unroll
    for (int k = 0; k < 8; k++)
        ws[k] = *(const float4*)(wsal + k * 128 + lane * 4);
    float4 cs[8];
#pragma unroll
    for (int k = 0; k < 8; k++) cs[k] = make_float4(0.f, 0.f, 0.f, 0.f);

    __syncthreads();

    const int row0 = blockIdx.x * 64 + warp * 8;
#pragma unroll
    for (int r = 0; r < 8; r++) {
        const int t = row0 + r;
        const float* src = (t < A_)
            ? active + ((size_t)b * A_ + t) * D_
            : x      + ((size_t)b * L_ + (t - A_)) * D_;
        float dot = 0.f;
#pragma unroll
        for (int k = 0; k < 8; k++) {
            float4 v = *(const float4*)(src + k * 128 + lane * 4);
            dot += v.x * ws[k].x + v.y * ws[k].y + v.z * ws[k].z + v.w * ws[k].w;
            cs[k].x += v.x; cs[k].y += v.y; cs[k].z += v.z; cs[k].w += v.w;
        }
#pragma unroll
        for (int o = 16; o > 0; o >>= 1)
            dot += __shfl_down_sync(0xffffffffu, dot, o);
        if (lane == 0) g_sal[b * LC_ + t] = dot;
    }

#pragma unroll
    for (int k = 0; k < 8; k++) {
        int d0 = k * 128 + lane * 4;
        atomicAdd(&s_col[d0 + 0], cs[k].x);
        atomicAdd(&s_col[d0 + 1], cs[k].y);
        atomicAdd(&s_col[d0 + 2], cs[k].z);
        atomicAdd(&s_col[d0 + 3], cs[k].w);
    }
    __syncthreads();
    float* dst = g_part + ((size_t)b * NSLICE + blockIdx.x) * D_;
    for (int i = tid; i < D_ / 4; i += blockDim.x)
        *(float4*)(dst + i * 4) = *(const float4*)(&s_col[i * 4]);
}

// ---------------- K2: exact top-256 (radix select), sorted ascending ----------------
__device__ __forceinline__ unsigned int order_key(float f) {
    unsigned int u = __float_as_uint(f);
    return u ^ ((u >> 31) ? 0xFFFFFFFFu : 0x80000000u);
}

__global__ void k_topk() {
    const int b   = blockIdx.x;
    const int tid = threadIdx.x;
    const int nt  = blockDim.x;

    __shared__ unsigned int skeys[LC_];
    __shared__ int          eqbuf[LC_];
    __shared__ unsigned int hist[256];
    __shared__ unsigned int sscan[256 + 1];
    __shared__ int          out_idx[KEEP_];
    __shared__ unsigned int s_prefix;
    __shared__ int          s_krem, s_ngt, s_neq;

    for (int i = tid; i < LC_; i += nt)
        skeys[i] = order_key(g_sal[b * LC_ + i]);
    if (tid == 0) { s_prefix = 0u; s_krem = KEEP_; s_ngt = 0; s_neq = 0; }
    if (tid == 256) sscan[256] = 0u;
    __syncthreads();

    for (int pass = 0; pass < 4; pass++) {
        const int shift = 24 - 8 * pass;
        if (tid < 256) hist[tid] = 0u;
        __syncthreads();
        const unsigned int pfx = s_prefix;
        const int krem = s_krem;
        for (int i = tid; i < LC_; i += nt) {
            unsigned int k = skeys[i];
            if (pass == 0 || (k >> (shift + 8)) == pfx)
                atomicAdd(&hist[(k >> shift) & 255u], 1u);
        }
        __syncthreads();

        // parallel suffix scan: sscan[d] = sum_{e>=d} hist[e]
        if (tid < 256) sscan[tid] = hist[tid];
        __syncthreads();
#pragma unroll
        for (int off = 1; off < 256; off <<= 1) {
            unsigned int v = 0u;
            if (tid < 256) {
                v = sscan[tid];
                if (tid + off < 256) v += sscan[tid + off];
            }
            __syncthreads();
            if (tid < 256) sscan[tid] = v;
            __syncthreads();
        }
        // unique crossing bucket: sscan[d] >= krem > sscan[d+1]
        if (tid < 256) {
            unsigned int s  = sscan[tid];
            unsigned int sn = sscan[tid + 1];
            if (s >= (unsigned int)krem && sn < (unsigned int)krem) {
                s_prefix = (pfx << 8) | (unsigned int)tid;
                s_krem   = krem - (int)sn;
            }
        }
        __syncthreads();
    }

    const unsigned int thr = s_prefix;
    const int rem = s_krem;

    for (int i = tid; i < LC_; i += nt) {
        unsigned int k = skeys[i];
        if (k > thr)       { int p = atomicAdd(&s_ngt, 1); out_idx[p] = i; }
        else if (k == thr) { int p = atomicAdd(&s_neq, 1); eqbuf[p]   = i; }
    }
    __syncthreads();
    const int ngt = s_ngt, neq = s_neq;
    for (int j = tid; j < neq; j += nt) {
        int v = eqbuf[j], c = 0;
        for (int m = 0; m < neq; m++) c += (eqbuf[m] < v);
        if (c < rem) out_idx[ngt + c] = v;
    }
    __syncthreads();

    for (int k = 2; k <= KEEP_; k <<= 1) {
        for (int j = k >> 1; j > 0; j >>= 1) {
            for (int t = tid; t < KEEP_; t += nt) {
                int partner = t ^ j;
                if (partner > t) {
                    int a0 = out_idx[t], a1 = out_idx[partner];
                    bool up = ((t & k) == 0);
                    if ((a0 > a1) == up) { out_idx[t] = a1; out_idx[partner] = a0; }
                }
            }
            __syncthreads();
        }
    }
    for (int t = tid; t < KEEP_; t += nt)
        g_topidx[b * KEEP_ + t] = out_idx[t];
}

// ---------------- K3: gather kept rows + per-block kept column sums ----------------
// grid: (GSLICE, B_) = (32, B_), block 256 (8 warps); warp w copies row blk*8+w
__global__ void k_gather(const float* __restrict__ x,
                         const float* __restrict__ active,
                         float* __restrict__ new_active_out) {
    __shared__ float s_col[D_];
    const int b    = blockIdx.y;
    const int tid  = threadIdx.x;
    const int warp = tid >> 5;
    const int lane = tid & 31;
    const int row  = blockIdx.x * 8 + warp;

    for (int i = tid; i < D_; i += blockDim.x) s_col[i] = 0.f;

    const int idx = g_topidx[b * KEEP_ + row];
    const float* src = (idx < A_)
        ? active + ((size_t)b * A_ + idx) * D_
        : x      + ((size_t)b * L_ + (idx - A_)) * D_;
    float* dst = new_active_out + ((size_t)b * KEEP_ + row) * D_;

    float4 v[8];
#pragma unroll
    for (int k = 0; k < 8; k++)
        v[k] = *(const float4*)(src + k * 128 + lane * 4);
    __syncthreads();
#pragma unroll
    for (int k = 0; k < 8; k++) {
        *(float4*)(dst + k * 128 + lane * 4) = v[k];
        int d0 = k * 128 + lane * 4;
        atomicAdd(&s_col[d0 + 0], v[k].x);
        atomicAdd(&s_col[d0 + 1], v[k].y);
        atomicAdd(&s_col[d0 + 2], v[k].z);
        atomicAdd(&s_col[d0 + 3], v[k].w);
    }
    __syncthreads();
    float* kp = g_kpart + ((size_t)b * GSLICE + blockIdx.x) * D_;
    for (int i = tid; i < D_ / 4; i += blockDim.x)
        *(float4*)(kp + i * 4) = *(const float4*)(&s_col[i * 4]);
}

// ---------------- K4: reduce partials -> cold_new + ctx ----------------
// grid (D_/64, B_) = (16, B_), block 512: 8 threads cooperate per d (64 d per block)
__global__ void k_ctx(const float* __restrict__ cold,
                      float* __restrict__ cold_out) {
    __shared__ float st[8][64];
    __shared__ float sk[8][64];
    const int b  = blockIdx.y;
    const int d0 = blockIdx.x * 64;
    const int dx = threadIdx.x & 63;
    const int sy = threadIdx.x >> 6;

    float tot = 0.f;
    const float* p = g_part + (size_t)b * NSLICE * D_ + d0 + dx;
#pragma unroll
    for (int s = sy; s < NSLICE; s += 8) tot += p[(size_t)s * D_];

    float ks = 0.f;
    const float* kp = g_kpart + (size_t)b * GSLICE * D_ + d0 + dx;
#pragma unroll
    for (int s = sy; s < GSLICE; s += 8) ks += kp[(size_t)s * D_];

    st[sy][dx] = tot;
    sk[sy][dx] = ks;
    __syncthreads();
    if (sy == 0) {
        float t = 0.f, k = 0.f;
#pragma unroll
        for (int s = 0; s < 8; s++) { t += st[s][dx]; k += sk[s][dx]; }
        const int i = b * D_ + d0 + dx;
        const float dropped_mean = (t - k) * (1.0f / (float)(LC_ - KEEP_));
        const float cn = 0.9f * cold[i] + 0.1f * dropped_mean;
        cold_out[i] = cn;
        g_ctx[i] = k * (1.0f / (float)KEEP_) + cn;
    }
}

// ---------------- K5: proj[b,e] = sum_d ctx[b,d] * w_read[e,d] ----------------
// grid 32, block 256 (8 warps, 4 rows each)
__global__ void k_gemv(const float* __restrict__ wread) {
    __shared__ float4 sctx[B_ * 256];
    const int tid = threadIdx.x;
    for (int i = tid; i < B_ * 256; i += blockDim.x)
        sctx[i] = *(const float4*)(g_ctx + i * 4);
    __syncthreads();

    const int warp = tid >> 5, lane = tid & 31;
    for (int r = 0; r < 4; r++) {
        const int e = blockIdx.x * 32 + warp * 4 + r;
        const float* wr = wread + (size_t)e * D_;
        float acc[B_];
#pragma unroll
        for (int bb = 0; bb < B_; bb++) acc[bb] = 0.f;
#pragma unroll
        for (int k = 0; k < 8; k++) {
            float4 w = *(const float4*)(wr + k * 128 + lane * 4);
#pragma unroll
            for (int bb = 0; bb < B_; bb++) {
                float4 c = sctx[bb * 256 + k * 32 + lane];
                acc[bb] += w.x * c.x + w.y * c.y + w.z * c.z + w.w * c.w;
            }
        }
#pragma unroll
        for (int bb = 0; bb < B_; bb++) {
#pragma unroll
            for (int o = 16; o > 0; o >>= 1)
                acc[bb] += __shfl_down_sync(0xffffffffu, acc[bb], o);
            if (lane == 0) g_proj[bb * D_ + e] = acc[bb];
        }
    }
}

// ---------------- K6: x_out = x + proj (broadcast over l) ----------------
// grid: (L_/16, B_), block 256; 16 rows per block; MLP-8 prefetch
__global__ void k_addproj(const float* __restrict__ x,
                          float* __restrict__ xout) {
    const int b   = blockIdx.y;
    const int l0  = blockIdx.x * 16;
    const int tid = threadIdx.x;
    const float4 p = *(const float4*)(g_proj + b * D_ + tid * 4);
    const float* xs = x    + ((size_t)b * L_ + l0) * D_ + tid * 4;
    float*       os = xout + ((size_t)b * L_ + l0) * D_ + tid * 4;
#pragma unroll
    for (int rr = 0; rr < 16; rr += 8) {
        float4 v[8];
#pragma unroll
        for (int r = 0; r < 8; r++)
            v[r] = *(const float4*)(xs + (size_t)(rr + r) * D_);
#pragma unroll
        for (int r = 0; r < 8; r++) {
            v[r].x += p.x; v[r].y += p.y; v[r].z += p.z; v[r].w += p.w;
            *(float4*)(os + (size_t)(rr + r) * D_) = v[r];
        }
    }
}

// ---------------- launch ----------------
extern "C" void kernel_launch(void* const* d_in, const int* in_sizes, int n_in,
                              void* d_out, int out_size) {
    const float* x      = (const float*)d_in[0];   // [8,4096,1024]
    const float* active = (const float*)d_in[1];   // [8,256,1024]
    const float* cold   = (const float*)d_in[2];   // [8,1024]
    const float* w_sal  = (const float*)d_in[3];   // [1024]
    const float* w_read = (const float*)d_in[4];   // [1024,1024]

    float* xout       = (float*)d_out;
    float* new_active = xout + (size_t)in_sizes[0];
    float* cold_out   = new_active + (size_t)in_sizes[1];

    { dim3 grid(NSLICE, B_); k_salience<<<grid, 256>>>(x, active, w_sal); }
    k_topk<<<B_, 1024>>>();
    { dim3 grid(GSLICE, B_); k_gather<<<grid, 256>>>(x, active, new_active); }
    { dim3 grid(D_ / 64, B_); k_ctx<<<grid, 512>>>(cold, cold_out); }
    k_gemv<<<32, 256>>>(w_read);
    { dim3 grid(L_ / 16, B_); k_addproj<<<grid, 256>>>(x, xout); }
}

// round 5
// speedup vs baseline: 1.7275x; 1.1712x over previous
#include <cuda_runtime.h>
#include <cuda_bf16.h>
#include <stdint.h>

#define B_    8
#define L_    4096
#define D_    1024
#define A_    256
#define LC_   4352      // A_ + L_
#define KEEP_ 256
#define NSLICE 34       // salience partial slices (34 * 128 rows = 4352)
#define GSLICE 32       // gather partial slices  (32 * 8 rows = 256)

// -------- scratch (device globals; no allocation allowed) --------
__device__ float g_sal[B_ * LC_];
__device__ float g_part[B_ * NSLICE * D_];   // salience per-block column sums
__device__ float g_kpart[B_ * GSLICE * D_];  // gather per-block kept column sums
__device__ int   g_topidx[B_ * KEEP_];
__device__ float g_ctx[B_ * D_];
__device__ float g_proj[B_ * D_];

// ---------------- K1: salience + per-block partial column sums ----------------
// grid: (NSLICE, B_), block 512 (16 warps). 128 rows/block, 8 rows/warp.
__global__ void k_salience(const float* __restrict__ x,
                           const float* __restrict__ active,
                           const float* __restrict__ wsal) {
    __shared__ float s_col[D_];
    const int b    = blockIdx.y;
    const int tid  = threadIdx.x;
    const int warp = tid >> 5;
    const int lane = tid & 31;

    for (int i = tid; i < D_; i += blockDim.x) s_col[i] = 0.f;

    float4 ws[8];
#pragma unroll
    for (int k = 0; k < 8; k++)
        ws[k] = *(const float4*)(wsal + k * 128 + lane * 4);
    float4 cs[8];
#pragma unroll
    for (int k = 0; k < 8; k++) cs[k] = make_float4(0.f, 0.f, 0.f, 0.f);

    __syncthreads();

    const int row0 = blockIdx.x * 128 + warp * 8;
#pragma unroll
    for (int r = 0; r < 8; r++) {
        const int t = row0 + r;
        const float* src = (t < A_)
            ? active + ((size_t)b * A_ + t) * D_
            : x      + ((size_t)b * L_ + (t - A_)) * D_;
        float dot = 0.f;
#pragma unroll
        for (int k = 0; k < 8; k++) {
            float4 v = *(const float4*)(src + k * 128 + lane * 4);
            dot += v.x * ws[k].x + v.y * ws[k].y + v.z * ws[k].z + v.w * ws[k].w;
            cs[k].x += v.x; cs[k].y += v.y; cs[k].z += v.z; cs[k].w += v.w;
        }
#pragma unroll
        for (int o = 16; o > 0; o >>= 1)
            dot += __shfl_down_sync(0xffffffffu, dot, o);
        if (lane == 0) g_sal[b * LC_ + t] = dot;
    }

#pragma unroll
    for (int k = 0; k < 8; k++) {
        int d0 = k * 128 + lane * 4;
        atomicAdd(&s_col[d0 + 0], cs[k].x);
        atomicAdd(&s_col[d0 + 1], cs[k].y);
        atomicAdd(&s_col[d0 + 2], cs[k].z);
        atomicAdd(&s_col[d0 + 3], cs[k].w);
    }
    __syncthreads();
    float* dst = g_part + ((size_t)b * NSLICE + blockIdx.x) * D_;
    for (int i = tid; i < D_ / 4; i += blockDim.x)
        *(float4*)(dst + i * 4) = *(const float4*)(&s_col[i * 4]);
}

// ---------------- K2: exact top-256 (radix select), sorted ascending ----------------
__device__ __forceinline__ unsigned int order_key(float f) {
    unsigned int u = __float_as_uint(f);
    return u ^ ((u >> 31) ? 0xFFFFFFFFu : 0x80000000u);
}

__global__ void k_topk() {
    const int b    = blockIdx.x;
    const int tid  = threadIdx.x;           // 1024 threads
    const int lane = tid & 31;
    const int warp = tid >> 5;

    __shared__ unsigned int skeys[LC_];
    __shared__ unsigned int hist[256];
    __shared__ int          out_idx[KEEP_];
    __shared__ unsigned int wsum[32];
    __shared__ unsigned int s_prefix;
    __shared__ int          s_krem;

    for (int i = tid; i < LC_; i += 1024)
        skeys[i] = order_key(g_sal[b * LC_ + i]);
    if (tid == 0) { s_prefix = 0u; s_krem = KEEP_; }
    __syncthreads();

    // 4-pass radix select, bucket scan by warp 0 (shuffle suffix-scan)
    for (int pass = 0; pass < 4; pass++) {
        const int shift = 24 - 8 * pass;
        if (tid < 256) hist[tid] = 0u;
        __syncthreads();
        const unsigned int pfx = s_prefix;
        const int krem = s_krem;
        for (int i = tid; i < LC_; i += 1024) {
            unsigned int k = skeys[i];
            if (pass == 0 || (k >> (shift + 8)) == pfx)
                atomicAdd(&hist[(k >> shift) & 255u], 1u);
        }
        __syncthreads();
        if (warp == 0) {
            unsigned int h[8], suf[8];
            unsigned int acc = 0u;
#pragma unroll
            for (int j = 7; j >= 0; j--) { h[j] = hist[lane * 8 + j]; acc += h[j]; suf[j] = acc; }
            const unsigned int tot = acc;
            unsigned int inc = tot;
#pragma unroll
            for (int off = 1; off < 32; off <<= 1) {
                unsigned int v = __shfl_down_sync(0xffffffffu, inc, off);
                if (lane + off < 32) inc += v;
            }
            const unsigned int after = inc - tot;  // sum over lanes > lane
#pragma unroll
            for (int j = 0; j < 8; j++) {
                unsigned int S  = after + suf[j];
                unsigned int Sn = after + (j < 7 ? suf[j + 1] : 0u);
                if (S >= (unsigned int)krem && Sn < (unsigned int)krem) {
                    s_prefix = (pfx << 8) | (unsigned int)(lane * 8 + j);
                    s_krem   = krem - (int)Sn;
                }
            }
        }
        __syncthreads();
    }

    const unsigned int thr = s_prefix;
    const unsigned int rem = (unsigned int)s_krem;

    // blocked (gt,eq) pair prefix scan; writes kept indices in ascending order
    const int base = tid * 5;                 // 1024*5 = 5120 >= LC_
    unsigned int keys_l[5];
    unsigned int gt = 0u, eq = 0u;
#pragma unroll
    for (int j = 0; j < 5; j++) {
        const int i = base + j;
        unsigned int k = (i < LC_) ? skeys[i] : 0u;
        keys_l[j] = k;
        if (i < LC_) { gt += (k > thr); eq += (k == thr); }
    }
    const unsigned int pair = (gt << 16) | eq;
    unsigned int inc = pair;
#pragma unroll
    for (int off = 1; off < 32; off <<= 1) {
        unsigned int v = __shfl_up_sync(0xffffffffu, inc, off);
        if (lane >= off) inc += v;
    }
    const unsigned int excl = inc - pair;
    if (lane == 31) wsum[warp] = inc;
    __syncthreads();
    if (warp == 0) {
        unsigned int v = wsum[lane];
        unsigned int winc = v;
#pragma unroll
        for (int off = 1; off < 32; off <<= 1) {
            unsigned int t = __shfl_up_sync(0xffffffffu, winc, off);
            if (lane >= off) winc += t;
        }
        wsum[lane] = winc - v;   // exclusive
    }
    __syncthreads();
    const unsigned int basepair = excl + wsum[warp];
    unsigned int gpref = basepair >> 16;
    unsigned int epref = basepair & 0xFFFFu;
#pragma unroll
    for (int j = 0; j < 5; j++) {
        const int i = base + j;
        if (i < LC_) {
            const unsigned int k = keys_l[j];
            if (k > thr) {
                out_idx[gpref + (epref < rem ? epref : rem)] = i;
                gpref++;
            } else if (k == thr) {
                if (epref < rem) out_idx[gpref + epref] = i;
                epref++;
            }
        }
    }
    __syncthreads();
    if (tid < KEEP_) g_topidx[b * KEEP_ + tid] = out_idx[tid];
}

// ---------------- K3: gather kept rows + per-block kept column sums ----------------
// grid: (GSLICE, B_) = (32, B_), block 256 (8 warps); warp w copies row blk*8+w
__global__ void k_gather(const float* __restrict__ x,
                         const float* __restrict__ active,
                         float* __restrict__ new_active_out) {
    __shared__ float s_col[D_];
    const int b    = blockIdx.y;
    const int tid  = threadIdx.x;
    const int warp = tid >> 5;
    const int lane = tid & 31;
    const int row  = blockIdx.x * 8 + warp;

    for (int i = tid; i < D_; i += blockDim.x) s_col[i] = 0.f;

    const int idx = g_topidx[b * KEEP_ + row];
    const float* src = (idx < A_)
        ? active + ((size_t)b * A_ + idx) * D_
        : x      + ((size_t)b * L_ + (idx - A_)) * D_;
    float* dst = new_active_out + ((size_t)b * KEEP_ + row) * D_;

    float4 v[8];
#pragma unroll
    for (int k = 0; k < 8; k++)
        v[k] = *(const float4*)(src + k * 128 + lane * 4);
    __syncthreads();
#pragma unroll
    for (int k = 0; k < 8; k++) {
        *(float4*)(dst + k * 128 + lane * 4) = v[k];
        int d0 = k * 128 + lane * 4;
        atomicAdd(&s_col[d0 + 0], v[k].x);
        atomicAdd(&s_col[d0 + 1], v[k].y);
        atomicAdd(&s_col[d0 + 2], v[k].z);
        atomicAdd(&s_col[d0 + 3], v[k].w);
    }
    __syncthreads();
    float* kp = g_kpart + ((size_t)b * GSLICE + blockIdx.x) * D_;
    for (int i = tid; i < D_ / 4; i += blockDim.x)
        *(float4*)(kp + i * 4) = *(const float4*)(&s_col[i * 4]);
}

// ---------------- K4: reduce partials -> cold_new + ctx ----------------
// grid (D_/64, B_) = (16, B_), block 512: 8 threads cooperate per d (64 d per block)
__global__ void k_ctx(const float* __restrict__ cold,
                      float* __restrict__ cold_out) {
    __shared__ float st[8][64];
    __shared__ float sk[8][64];
    const int b  = blockIdx.y;
    const int d0 = blockIdx.x * 64;
    const int dx = threadIdx.x & 63;
    const int sy = threadIdx.x >> 6;

    float tot = 0.f;
    const float* p = g_part + (size_t)b * NSLICE * D_ + d0 + dx;
#pragma unroll
    for (int s = sy; s < NSLICE; s += 8) tot += p[(size_t)s * D_];

    float ks = 0.f;
    const float* kp = g_kpart + (size_t)b * GSLICE * D_ + d0 + dx;
#pragma unroll
    for (int s = sy; s < GSLICE; s += 8) ks += kp[(size_t)s * D_];

    st[sy][dx] = tot;
    sk[sy][dx] = ks;
    __syncthreads();
    if (sy == 0) {
        float t = 0.f, k = 0.f;
#pragma unroll
        for (int s = 0; s < 8; s++) { t += st[s][dx]; k += sk[s][dx]; }
        const int i = b * D_ + d0 + dx;
        const float dropped_mean = (t - k) * (1.0f / (float)(LC_ - KEEP_));
        const float cn = 0.9f * cold[i] + 0.1f * dropped_mean;
        cold_out[i] = cn;
        g_ctx[i] = k * (1.0f / (float)KEEP_) + cn;
    }
}

// ---------------- K5: proj[b,e] = sum_d ctx[b,d] * w_read[e,d] ----------------
// grid 128, block 256 (8 warps, 1 row each)
__global__ void k_gemv(const float* __restrict__ wread) {
    __shared__ float4 sctx[B_ * 256];
    const int tid = threadIdx.x;
    for (int i = tid; i < B_ * 256; i += blockDim.x)
        sctx[i] = *(const float4*)(g_ctx + i * 4);
    __syncthreads();

    const int warp = tid >> 5, lane = tid & 31;
    const int e = blockIdx.x * 8 + warp;
    const float* wr = wread + (size_t)e * D_;
    float acc[B_];
#pragma unroll
    for (int bb = 0; bb < B_; bb++) acc[bb] = 0.f;
#pragma unroll
    for (int k = 0; k < 8; k++) {
        float4 w = *(const float4*)(wr + k * 128 + lane * 4);
#pragma unroll
        for (int bb = 0; bb < B_; bb++) {
            float4 c = sctx[bb * 256 + k * 32 + lane];
            acc[bb] += w.x * c.x + w.y * c.y + w.z * c.z + w.w * c.w;
        }
    }
#pragma unroll
    for (int bb = 0; bb < B_; bb++) {
#pragma unroll
        for (int o = 16; o > 0; o >>= 1)
            acc[bb] += __shfl_down_sync(0xffffffffu, acc[bb], o);
        if (lane == 0) g_proj[bb * D_ + e] = acc[bb];
    }
}

// ---------------- K6: x_out = x + proj (broadcast over l) ----------------
// grid: (L_/32, B_) = (128, B_), block 256; 32 rows per block; MLP-8 prefetch
__global__ void k_addproj(const float* __restrict__ x,
                          float* __restrict__ xout) {
    const int b   = blockIdx.y;
    const int l0  = blockIdx.x * 32;
    const int tid = threadIdx.x;
    const float4 p = *(const float4*)(g_proj + b * D_ + tid * 4);
    const float* xs = x    + ((size_t)b * L_ + l0) * D_ + tid * 4;
    float*       os = xout + ((size_t)b * L_ + l0) * D_ + tid * 4;
#pragma unroll
    for (int rr = 0; rr < 32; rr += 8) {
        float4 v[8];
#pragma unroll
        for (int r = 0; r < 8; r++)
            v[r] = *(const float4*)(xs + (size_t)(rr + r) * D_);
#pragma unroll
        for (int r = 0; r < 8; r++) {
            v[r].x += p.x; v[r].y += p.y; v[r].z += p.z; v[r].w += p.w;
            *(float4*)(os + (size_t)(rr + r) * D_) = v[r];
        }
    }
}

// ---------------- launch ----------------
extern "C" void kernel_launch(void* const* d_in, const int* in_sizes, int n_in,
                              void* d_out, int out_size) {
    const float* x      = (const float*)d_in[0];   // [8,4096,1024]
    const float* active = (const float*)d_in[1];   // [8,256,1024]
    const float* cold   = (const float*)d_in[2];   // [8,1024]
    const float* w_sal  = (const float*)d_in[3];   // [1024]
    const float* w_read = (const float*)d_in[4];   // [1024,1024]

    float* xout       = (float*)d_out;
    float* new_active = xout + (size_t)in_sizes[0];
    float* cold_out   = new_active + (size_t)in_sizes[1];

    { dim3 grid(NSLICE, B_); k_salience<<<grid, 512>>>(x, active, w_sal); }
    k_topk<<<B_, 1024>>>();
    { dim3 grid(GSLICE, B_); k_gather<<<grid, 256>>>(x, active, new_active); }
    { dim3 grid(D_ / 64, B_); k_ctx<<<grid, 512>>>(cold, cold_out); }
    k_gemv<<<128, 256>>>(w_read);
    { dim3 grid(L_ / 32, B_); k_addproj<<<grid, 256>>>(x, xout); }
}